// round 1
// baseline (speedup 1.0000x reference)
#include <cuda_runtime.h>

// Problem constants
#define TT 128
#define BB 512
#define DD 768

// Scratch (device globals — no runtime allocation allowed)
__device__ float g_G[(size_t)TT * BB * 64];  // fused input-proj gates: [t][b][64], cols 0-31 fwd, 32-63 bwd (bias included)
__device__ float g_h[(size_t)TT * BB * 16];  // bi-LSTM hidden: [t][b][16], cols 0-7 fwd, 8-15 bwd
__device__ float g_z[(size_t)TT * BB * 16];  // ptr-LSTM hidden: [t][b][16]

__device__ __forceinline__ float sigmoidf_fast(float x) {
    return 1.0f / (1.0f + __expf(-x));
}

// ---------------------------------------------------------------------------
// K1: fused input projection for fwd+bwd bi-LSTM.
// G[r][j] = X[r] . Wcat[j] + bias[j],  r = t*B+b (65536 rows), j in [0,64)
// Wcat rows 0-31 = Wih_f, 32-63 = Wih_b. Classic smem-tiled GEMM,
// BM=64, BN=64, BK=16, 256 threads, 4x4 microtile.
// ---------------------------------------------------------------------------
__global__ __launch_bounds__(256) void k1_proj(
    const float* __restrict__ X,
    const float* __restrict__ Wf, const float* __restrict__ Wb,
    const float* __restrict__ bf1, const float* __restrict__ bf2,
    const float* __restrict__ bb1, const float* __restrict__ bb2)
{
    __shared__ float As[16][64];  // As[k][m]
    __shared__ float Bs[16][64];  // Bs[k][n]

    const int tid  = threadIdx.x;
    const int row0 = blockIdx.x * 64;
    const int lrow = tid >> 2;   // 0..63 (row for X load / col for W load)
    const int c4   = tid & 3;    // 0..3 (which 4-float chunk of the 16-wide K tile)

    const float* wsrc = (lrow < 32) ? (Wf + (size_t)lrow * DD)
                                    : (Wb + (size_t)(lrow - 32) * DD);
    const float* xsrc = X + (size_t)(row0 + lrow) * DD;

    const int ty = tid >> 4;     // 0..15 -> rows ty*4..+3
    const int tx = tid & 15;     // 0..15 -> cols tx*4..+3

    float acc[4][4];
#pragma unroll
    for (int i = 0; i < 4; i++)
#pragma unroll
        for (int j = 0; j < 4; j++) acc[i][j] = 0.0f;

    for (int k0 = 0; k0 < DD; k0 += 16) {
        float4 xa = *(const float4*)(xsrc + k0 + c4 * 4);
        float4 wa = *(const float4*)(wsrc + k0 + c4 * 4);
        __syncthreads();
        As[c4 * 4 + 0][lrow] = xa.x;
        As[c4 * 4 + 1][lrow] = xa.y;
        As[c4 * 4 + 2][lrow] = xa.z;
        As[c4 * 4 + 3][lrow] = xa.w;
        Bs[c4 * 4 + 0][lrow] = wa.x;
        Bs[c4 * 4 + 1][lrow] = wa.y;
        Bs[c4 * 4 + 2][lrow] = wa.z;
        Bs[c4 * 4 + 3][lrow] = wa.w;
        __syncthreads();
#pragma unroll
        for (int kk = 0; kk < 16; kk++) {
            float4 av = *(const float4*)&As[kk][ty * 4];
            float4 bv = *(const float4*)&Bs[kk][tx * 4];
            float a[4] = {av.x, av.y, av.z, av.w};
            float b[4] = {bv.x, bv.y, bv.z, bv.w};
#pragma unroll
            for (int i = 0; i < 4; i++)
#pragma unroll
                for (int j = 0; j < 4; j++)
                    acc[i][j] = fmaf(a[i], b[j], acc[i][j]);
        }
    }

    // bias for the 4 output columns of this thread
    float bias[4];
#pragma unroll
    for (int jj = 0; jj < 4; jj++) {
        int j = tx * 4 + jj;
        bias[jj] = (j < 32) ? (bf1[j] + bf2[j]) : (bb1[j - 32] + bb2[j - 32]);
    }
#pragma unroll
    for (int i = 0; i < 4; i++) {
        int gr = row0 + ty * 4 + i;
        float4 o;
        o.x = acc[i][0] + bias[0];
        o.y = acc[i][1] + bias[1];
        o.z = acc[i][2] + bias[2];
        o.w = acc[i][3] + bias[3];
        *(float4*)(g_G + (size_t)gr * 64 + tx * 4) = o;
    }
}

// ---------------------------------------------------------------------------
// K2: bi-LSTM scans (fwd + bwd), one warp per (batch item, direction).
// Lane j computes gate j (i:0-7, f:8-15, g:16-23, o:24-31). Hidden state
// replicated across lanes; updated via shuffles. G prefetched (double buffer).
// ---------------------------------------------------------------------------
__global__ __launch_bounds__(128) void k2_bilstm(
    const float* __restrict__ Whhf, const float* __restrict__ Whhb)
{
    const unsigned FULL = 0xffffffffu;
    int warp = blockIdx.x * (blockDim.x >> 5) + (threadIdx.x >> 5); // 0..1023
    int lane = threadIdx.x & 31;
    int dir  = warp >> 9;       // 0 fwd, 1 bwd
    int b    = warp & 511;

    const float* Whh = dir ? Whhb : Whhf;
    float w[8];
#pragma unroll
    for (int k = 0; k < 8; k++) w[k] = Whh[lane * 8 + k];

    float hrep[8];
#pragma unroll
    for (int k = 0; k < 8; k++) hrep[k] = 0.0f;
    float c = 0.0f;

    const int coloff = dir * 32 + lane;
    int t0 = dir ? (TT - 1) : 0;
    float gcur = g_G[((size_t)t0 * BB + b) * 64 + coloff];

    for (int s = 0; s < TT; s++) {
        int t = dir ? (TT - 1 - s) : s;
        float gnext = 0.0f;
        if (s + 1 < TT) {
            int tn = dir ? (TT - 2 - s) : (s + 1);
            gnext = g_G[((size_t)tn * BB + b) * 64 + coloff];
        }
        float gate = gcur;
#pragma unroll
        for (int k = 0; k < 8; k++) gate = fmaf(hrep[k], w[k], gate);

        float a = (lane >= 16 && lane < 24) ? tanhf(gate) : sigmoidf_fast(gate);
        float fv = __shfl_sync(FULL, a, lane + 8);
        float gv = __shfl_sync(FULL, a, lane + 16);
        float ov = __shfl_sync(FULL, a, lane + 24);

        float hnew = 0.0f;
        if (lane < 8) {
            c = fmaf(fv, c, a * gv);        // a = i on lanes 0-7
            hnew = ov * tanhf(c);
            g_h[((size_t)t * BB + b) * 16 + dir * 8 + lane] = hnew;
        }
#pragma unroll
        for (int k = 0; k < 8; k++) hrep[k] = __shfl_sync(FULL, hnew, k);
        gcur = gnext;
    }
}

// ---------------------------------------------------------------------------
// K4: ptr-LSTM scan (unidirectional, in 16 -> hidden 16), one warp per batch
// item. Lane l computes gates l and l+32 (i/g for l<16, f/o for l>=16).
// Input projection (Wih_p) folded into the scan. h prefetched per step.
// ---------------------------------------------------------------------------
__global__ __launch_bounds__(128) void k4_ptr(
    const float* __restrict__ Wih, const float* __restrict__ Whh,
    const float* __restrict__ b1, const float* __restrict__ b2)
{
    const unsigned FULL = 0xffffffffu;
    int warp = blockIdx.x * (blockDim.x >> 5) + (threadIdx.x >> 5); // 0..511
    int lane = threadIdx.x & 31;
    int b    = warp;

    const int r0 = lane, r1 = lane + 32;
    float wi0[16], wi1[16], wh0[16], wh1[16];
#pragma unroll
    for (int k = 0; k < 16; k++) {
        wi0[k] = Wih[r0 * 16 + k];
        wi1[k] = Wih[r1 * 16 + k];
        wh0[k] = Whh[r0 * 16 + k];
        wh1[k] = Whh[r1 * 16 + k];
    }
    const float bias0 = b1[r0] + b2[r0];
    const float bias1 = b1[r1] + b2[r1];

    float zrep[16];
#pragma unroll
    for (int k = 0; k < 16; k++) zrep[k] = 0.0f;
    float c = 0.0f;

    const float4* hp = (const float4*)g_h;
    size_t base = ((size_t)0 * BB + b) * 4;
    float4 x0 = hp[base + 0], x1 = hp[base + 1], x2 = hp[base + 2], x3 = hp[base + 3];

    for (int t = 0; t < TT; t++) {
        float4 n0 = x0, n1 = x1, n2 = x2, n3 = x3;
        if (t + 1 < TT) {
            size_t nb = ((size_t)(t + 1) * BB + b) * 4;
            n0 = hp[nb + 0]; n1 = hp[nb + 1]; n2 = hp[nb + 2]; n3 = hp[nb + 3];
        }
        float xin[16] = {x0.x, x0.y, x0.z, x0.w, x1.x, x1.y, x1.z, x1.w,
                         x2.x, x2.y, x2.z, x2.w, x3.x, x3.y, x3.z, x3.w};
        float u0 = bias0, u1 = bias1;
#pragma unroll
        for (int k = 0; k < 16; k++) {
            u0 = fmaf(xin[k], wi0[k], u0);
            u1 = fmaf(xin[k], wi1[k], u1);
        }
#pragma unroll
        for (int k = 0; k < 16; k++) {
            u0 = fmaf(zrep[k], wh0[k], u0);
            u1 = fmaf(zrep[k], wh1[k], u1);
        }
        float a0 = sigmoidf_fast(u0);                               // i (l<16) or f (l>=16)
        float a1 = (lane < 16) ? tanhf(u1) : sigmoidf_fast(u1);     // g or o
        float fv = __shfl_sync(FULL, a0, lane + 16);
        float ov = __shfl_sync(FULL, a1, lane + 16);

        float zn = 0.0f;
        if (lane < 16) {
            c = fmaf(fv, c, a0 * a1);
            zn = ov * tanhf(c);
            g_z[((size_t)t * BB + b) * 16 + lane] = zn;
        }
#pragma unroll
        for (int k = 0; k < 16; k++) zrep[k] = __shfl_sync(FULL, zn, k);
        x0 = n0; x1 = n1; x2 = n2; x3 = n3;
    }
}

// ---------------------------------------------------------------------------
// K5: per-timestep attention + scoring. One block per t (128 blocks), 512
// threads (thread = query row b). Column-softmax over b needs column sums;
// scores are bounded (|h|,|z|<=1 -> |S|<=16) so no max-subtraction pass.
// E tile: 64 softmax-columns at a time, stride-520 padded for conflict-free
// strided column reduction. Each score computed exactly once.
// ---------------------------------------------------------------------------
#define K5_EPAD 520
#define K5_SMEM_FLOATS (8192 + 8192 + 64 * K5_EPAD + 512 + 64 + 528)
#define K5_SMEM_BYTES  (K5_SMEM_FLOATS * 4)

extern __shared__ float k5_smem[];

__global__ __launch_bounds__(512) void k5_attn(
    const float* __restrict__ Wh, const float* __restrict__ We,
    const float* __restrict__ Wv, float* __restrict__ out)
{
    float* hs  = k5_smem;                  // 512*16
    float* zs  = hs + 8192;                // 512*16
    float* E   = zs + 8192;                // 64 * 520
    float* red = E + 64 * K5_EPAD;         // 512
    float* inv = red + 512;                // 64
    float* ws  = inv + 64;                 // Wh[256] | We[256] | Wv[16]

    const int tid = threadIdx.x;
    const int t   = blockIdx.x;

    const float4* hg = (const float4*)(g_h + (size_t)t * BB * 16);
    const float4* zg = (const float4*)(g_z + (size_t)t * BB * 16);
    float4* hs4 = (float4*)hs;
    float4* zs4 = (float4*)zs;
    for (int i = tid; i < 2048; i += 512) {
        hs4[i] = hg[i];
        zs4[i] = zg[i];
    }
    if (tid < 256) ws[tid] = Wh[tid];
    else           ws[tid] = We[tid - 256];
    if (tid < 16)  ws[512 + tid] = Wv[tid];
    __syncthreads();

    const int bq = tid;
    float hr[16];
#pragma unroll
    for (int d = 0; d < 16; d++) hr[d] = hs[bq * 16 + d];
    float ctx[16];
#pragma unroll
    for (int d = 0; d < 16; d++) ctx[d] = 0.0f;

    for (int tile = 0; tile < 8; tile++) {
        // --- scores + exp for 64 softmax-columns ---
#pragma unroll 4
        for (int cc = 0; cc < 64; cc++) {
            const float4* zp = (const float4*)&zs[(tile * 64 + cc) * 16];
            float zz[16];
            *(float4*)&zz[0]  = zp[0];
            *(float4*)&zz[4]  = zp[1];
            *(float4*)&zz[8]  = zp[2];
            *(float4*)&zz[12] = zp[3];
            float dt = 0.0f;
#pragma unroll
            for (int d = 0; d < 16; d++) dt = fmaf(hr[d], zz[d], dt);
            E[cc * K5_EPAD + bq] = __expf(dt);
        }
        __syncthreads();
        // --- column sums (over b) ---
        {
            int cc = tid >> 3, seg = tid & 7;
            float s = 0.0f;
#pragma unroll 8
            for (int j = 0; j < 64; j++) s += E[cc * K5_EPAD + seg + 8 * j];
            red[tid] = s;
        }
        __syncthreads();
        if (tid < 64) {
            float s = 0.0f;
#pragma unroll
            for (int r = 0; r < 8; r++) s += red[tid * 8 + r];
            inv[tid] = 1.0f / s;
        }
        __syncthreads();
        // --- context accumulation ---
#pragma unroll 4
        for (int cc = 0; cc < 64; cc++) {
            float wv = E[cc * K5_EPAD + bq] * inv[cc];
            const float4* hp2 = (const float4*)&hs[(tile * 64 + cc) * 16];
            float hh[16];
            *(float4*)&hh[0]  = hp2[0];
            *(float4*)&hh[4]  = hp2[1];
            *(float4*)&hh[8]  = hp2[2];
            *(float4*)&hh[12] = hp2[3];
#pragma unroll
            for (int d = 0; d < 16; d++) ctx[d] = fmaf(wv, hh[d], ctx[d]);
        }
        __syncthreads();
    }

    // --- scoring epilogue: p = sigmoid( Wv . tanh(Wh h + We ctx) ) ---
    float p = 0.0f;
#pragma unroll
    for (int d = 0; d < 16; d++) {
        float s = 0.0f;
#pragma unroll
        for (int e = 0; e < 16; e++) s = fmaf(hr[e], ws[d * 16 + e], s);
#pragma unroll
        for (int e = 0; e < 16; e++) s = fmaf(ctx[e], ws[256 + d * 16 + e], s);
        p = fmaf(tanhf(s), ws[512 + d], p);
    }
    out[(size_t)t * BB + bq] = sigmoidf_fast(p);
}

// ---------------------------------------------------------------------------
extern "C" void kernel_launch(void* const* d_in, const int* in_sizes, int n_in,
                              void* d_out, int out_size)
{
    const float* X     = (const float*)d_in[0];
    const float* Wih_f = (const float*)d_in[1];
    const float* Whh_f = (const float*)d_in[2];
    const float* bih_f = (const float*)d_in[3];
    const float* bhh_f = (const float*)d_in[4];
    const float* Wih_b = (const float*)d_in[5];
    const float* Whh_b = (const float*)d_in[6];
    const float* bih_b = (const float*)d_in[7];
    const float* bhh_b = (const float*)d_in[8];
    const float* Wih_p = (const float*)d_in[9];
    const float* Whh_p = (const float*)d_in[10];
    const float* bih_p = (const float*)d_in[11];
    const float* bhh_p = (const float*)d_in[12];
    const float* W_h   = (const float*)d_in[13];
    const float* W_e   = (const float*)d_in[14];
    const float* W_v   = (const float*)d_in[15];
    float* out = (float*)d_out;

    cudaFuncSetAttribute(k5_attn, cudaFuncAttributeMaxDynamicSharedMemorySize,
                         K5_SMEM_BYTES);

    k1_proj<<<(TT * BB) / 64, 256>>>(X, Wih_f, Wih_b, bih_f, bhh_f, bih_b, bhh_b);
    k2_bilstm<<<256, 128>>>(Whh_f, Whh_b);
    k4_ptr<<<128, 128>>>(Wih_p, Whh_p, bih_p, bhh_p);
    k5_attn<<<TT, 512, K5_SMEM_BYTES>>>(W_h, W_e, W_v, out);
}